// round 8
// baseline (speedup 1.0000x reference)
#include <cuda_runtime.h>

// DiffJPEG forward: out = jpeg_compress(clip(x,0,1), quality=75)
// x, out: (16, 3, 512, 512) float32
//
// One CTA per 32x16 pixel region: 8 Y blocks + 2 Cb + 2 Cr (12 blocks of 8x8).
// 96 threads, one thread per block-row. Dot-product DCT/IDCT with immediate
// coefficients (high ILP); 8x8 transposes done with shfl_xor (zero L1 traffic).

#define IMG_H 512
#define IMG_W 512
#define BATCH 16

#define A1 0.4903926402016152f
#define A2 0.4619397662556434f
#define A3 0.4157348061512726f
#define A4 0.3535533905932738f
#define A5 0.2777851165098011f
#define A6 0.1913417161825449f
#define A7 0.0975451610080642f

__device__ constexpr float Dm[8][8] = {
    { A4,  A4,  A4,  A4,  A4,  A4,  A4,  A4},
    { A1,  A3,  A5,  A7, -A7, -A5, -A3, -A1},
    { A2,  A6, -A6, -A2, -A2, -A6,  A6,  A2},
    { A3, -A7, -A1, -A5,  A5,  A1,  A7, -A3},
    { A4, -A4, -A4,  A4,  A4, -A4, -A4,  A4},
    { A5, -A1,  A7,  A3, -A3, -A7,  A1, -A5},
    { A6, -A2,  A2, -A6, -A6,  A2, -A2,  A6},
    { A7, -A5,  A3, -A1,  A1, -A3,  A5, -A7},
};

__constant__ float c_QY[8][8] = {
    {16, 11, 10, 16, 24, 40, 51, 61},
    {12, 12, 14, 19, 26, 58, 60, 55},
    {14, 13, 16, 24, 40, 57, 69, 56},
    {14, 17, 22, 29, 51, 87, 80, 62},
    {18, 22, 37, 56, 68, 109, 103, 77},
    {24, 35, 55, 64, 81, 104, 113, 92},
    {49, 64, 78, 87, 103, 121, 120, 101},
    {72, 92, 95, 98, 112, 100, 103, 99},
};
__constant__ float c_QC[8][8] = {
    {17, 18, 24, 47, 99, 99, 99, 99},
    {18, 21, 26, 66, 99, 99, 99, 99},
    {24, 26, 56, 99, 99, 99, 99, 99},
    {47, 66, 99, 99, 99, 99, 99, 99},
    {99, 99, 99, 99, 99, 99, 99, 99},
    {99, 99, 99, 99, 99, 99, 99, 99},
    {99, 99, 99, 99, 99, 99, 99, 99},
    {99, 99, 99, 99, 99, 99, 99, 99},
};

// 8x8 transpose across the 8 lanes of a block (lanes are an aligned group of
// 8 within the warp; xor masks < 8 stay inside the group). 3 butterfly stages.
__device__ __forceinline__ void wtr8(float v[8], int lane8)
{
#pragma unroll
    for (int m = 1; m < 8; m <<= 1) {
        const bool hi = (lane8 & m) != 0;
#pragma unroll
        for (int j = 0; j < 8; j++) {
            if ((j & m) == 0) {
                const int jh = j | m;
                float tmp = hi ? v[j] : v[jh];
                float got = __shfl_xor_sync(0xffffffffu, tmp, m, 32);
                v[j]  = hi ? got  : v[j];
                v[jh] = hi ? v[jh] : got;
            }
        }
    }
}

// Full fwd-DCT -> quantize -> inv-DCT; thread holds row r of the block.
__device__ __forceinline__ void transform8(float v[8],
                                           const float (*Q)[9],
                                           const float (*Qi)[9], int r)
{
    float t[8];
    // row DCT: t[j] = sum_k v[k] * D[j][k]   (M1 = X * D^T, row r)
#pragma unroll
    for (int j = 0; j < 8; j++) {
        float s = 0.f;
#pragma unroll
        for (int k = 0; k < 8; k++) s += v[k] * Dm[j][k];
        t[j] = s;
    }
    wtr8(t, r);                                 // -> M1^T row r
    // column DCT -> coef[j][r]
#pragma unroll
    for (int j = 0; j < 8; j++) {
        float s = 0.f;
#pragma unroll
        for (int k = 0; k < 8; k++) s += t[k] * Dm[j][k];
        v[j] = s;
    }
    // quantize coef[j][r]
#pragma unroll
    for (int j = 0; j < 8; j++)
        v[j] = rintf(v[j] * Qi[j][r]) * Q[j][r];
    // column IDCT: t[j] = sum_k v[k] * D[k][j]
#pragma unroll
    for (int j = 0; j < 8; j++) {
        float s = 0.f;
#pragma unroll
        for (int k = 0; k < 8; k++) s += v[k] * Dm[k][j];
        t[j] = s;
    }
    wtr8(t, r);
    // row IDCT -> rec row r
#pragma unroll
    for (int j = 0; j < 8; j++) {
        float s = 0.f;
#pragma unroll
        for (int k = 0; k < 8; k++) s += t[k] * Dm[k][j];
        v[j] = s;
    }
}

__global__ __launch_bounds__(96, 8)
void diffjpeg_kernel(const float* __restrict__ x, float* __restrict__ out)
{
    __shared__ float sP[2][16][20];     // horizontally-averaged chroma partials
    __shared__ float sQ[2][8][9];       // quant tables * factor
    __shared__ float sQi[2][8][9];      // reciprocals
    __shared__ __align__(16) float sCrec[2][8][20];   // reconstructed chroma

    const int tid = threadIdx.x;
    const int bx0 = blockIdx.x * 32;
    const int by0 = blockIdx.y * 16;
    const size_t plane  = (size_t)IMG_H * IMG_W;
    const size_t ibase  = (size_t)blockIdx.z * 3 * plane;

    if (tid < 64) {
        int u = tid >> 3, vv = tid & 7;
        float qy = c_QY[u][vv] * 0.5f;   // quality 75 -> factor 0.5
        float qc = c_QC[u][vv] * 0.5f;
        sQ[0][u][vv]  = qy;
        sQ[1][u][vv]  = qc;
        sQi[0][u][vv] = 1.0f / qy;
        sQi[1][u][vv] = 1.0f / qc;
    }

    // luma geometry
    const int blk  = tid >> 3, r = tid & 7;
    const int bcol = blk & 3,  brow = blk >> 2;
    const int lrow = brow * 8 + r;

    float v[8];

    if (tid < 64) {
        // ---- luma: load row, color convert, emit chroma partials ----
        const float* pr = x + ibase + (size_t)(by0 + lrow) * IMG_W + (bx0 + bcol * 8);
        float cbh[4], crh[4];
#pragma unroll
        for (int h = 0; h < 2; h++) {
            float4 R4 = *(const float4*)(pr + 4 * h);
            float4 G4 = *(const float4*)(pr + plane + 4 * h);
            float4 B4 = *(const float4*)(pr + 2 * plane + 4 * h);
            float R[4] = {R4.x, R4.y, R4.z, R4.w};
            float G[4] = {G4.x, G4.y, G4.z, G4.w};
            float B[4] = {B4.x, B4.y, B4.z, B4.w};
            float cb[4], cr[4];
#pragma unroll
            for (int k = 0; k < 4; k++) {
                float rr = fminf(fmaxf(R[k], 0.f), 1.f) * 255.f;
                float gg = fminf(fmaxf(G[k], 0.f), 1.f) * 255.f;
                float bb = fminf(fmaxf(B[k], 0.f), 1.f) * 255.f;
                v[4 * h + k] =  0.299f    * rr + 0.587f    * gg + 0.114f    * bb - 128.f;
                cb[k]        = -0.168736f * rr - 0.331264f * gg + 0.5f      * bb + 128.f;
                cr[k]        =  0.5f      * rr - 0.418688f * gg - 0.081312f * bb + 128.f;
            }
            cbh[2 * h]     = 0.5f * (cb[0] + cb[1]);
            cbh[2 * h + 1] = 0.5f * (cb[2] + cb[3]);
            crh[2 * h]     = 0.5f * (cr[0] + cr[1]);
            crh[2 * h + 1] = 0.5f * (cr[2] + cr[3]);
        }
        *(float4*)&sP[0][lrow][bcol * 4] = make_float4(cbh[0], cbh[1], cbh[2], cbh[3]);
        *(float4*)&sP[1][lrow][bcol * 4] = make_float4(crh[0], crh[1], crh[2], crh[3]);
    }
    __syncthreads();

    if (tid < 64) {
        transform8(v, sQ[0], sQi[0], r);
    } else {
        // ---- chroma: finish 2x2 downsample, transform, publish ----
        const int t  = tid - 64;
        const int ch = t >> 4;
        const int s2 = t & 15;
        const int bc = s2 >> 3, cr_ = s2 & 7;

        float4 a0 = *(const float4*)&sP[ch][2 * cr_][bc * 8];
        float4 a1 = *(const float4*)&sP[ch][2 * cr_][bc * 8 + 4];
        float4 b0 = *(const float4*)&sP[ch][2 * cr_ + 1][bc * 8];
        float4 b1 = *(const float4*)&sP[ch][2 * cr_ + 1][bc * 8 + 4];

        v[0] = 0.5f * (a0.x + b0.x) - 128.f;
        v[1] = 0.5f * (a0.y + b0.y) - 128.f;
        v[2] = 0.5f * (a0.z + b0.z) - 128.f;
        v[3] = 0.5f * (a0.w + b0.w) - 128.f;
        v[4] = 0.5f * (a1.x + b1.x) - 128.f;
        v[5] = 0.5f * (a1.y + b1.y) - 128.f;
        v[6] = 0.5f * (a1.z + b1.z) - 128.f;
        v[7] = 0.5f * (a1.w + b1.w) - 128.f;

        transform8(v, sQ[1], sQi[1], cr_);

        *(float4*)&sCrec[ch][cr_][bc * 8]     = make_float4(v[0], v[1], v[2], v[3]);
        *(float4*)&sCrec[ch][cr_][bc * 8 + 4] = make_float4(v[4], v[5], v[6], v[7]);
    }
    __syncthreads();

    // ---- output: luma thread writes its own rec row directly ----
    if (tid < 64) {
        const int crow = lrow >> 1;
        float4 cb4 = *(const float4*)&sCrec[0][crow][bcol * 4];
        float4 cr4 = *(const float4*)&sCrec[1][crow][bcol * 4];
        float cbm[4] = {cb4.x, cb4.y, cb4.z, cb4.w};
        float crm[4] = {cr4.x, cr4.y, cr4.z, cr4.w};

        float* pw = out + ibase + (size_t)(by0 + lrow) * IMG_W + (bx0 + bcol * 8);
#pragma unroll
        for (int h = 0; h < 2; h++) {
            float Rr[4], Gg[4], Bb[4];
#pragma unroll
            for (int k = 0; k < 4; k++) {
                float cbv = cbm[2 * h + (k >> 1)];
                float crv = crm[2 * h + (k >> 1)];
                float yv = v[4 * h + k] + 128.f;
                float r2 = yv + 1.402f * crv;
                float g2 = yv - 0.344136f * cbv - 0.714136f * crv;
                float b2 = yv + 1.772f * cbv;
                Rr[k] = fminf(fmaxf(r2, 0.f), 255.f) * (1.f / 255.f);
                Gg[k] = fminf(fmaxf(g2, 0.f), 255.f) * (1.f / 255.f);
                Bb[k] = fminf(fmaxf(b2, 0.f), 255.f) * (1.f / 255.f);
            }
            *(float4*)(pw + 4 * h)             = make_float4(Rr[0], Rr[1], Rr[2], Rr[3]);
            *(float4*)(pw + plane + 4 * h)     = make_float4(Gg[0], Gg[1], Gg[2], Gg[3]);
            *(float4*)(pw + 2 * plane + 4 * h) = make_float4(Bb[0], Bb[1], Bb[2], Bb[3]);
        }
    }
}

extern "C" void kernel_launch(void* const* d_in, const int* in_sizes, int n_in,
                              void* d_out, int out_size)
{
    const float* x = (const float*)d_in[0];
    float* out = (float*)d_out;
    dim3 grid(IMG_W / 32, IMG_H / 16, BATCH);
    diffjpeg_kernel<<<grid, 96>>>(x, out);
}

// round 10
// speedup vs baseline: 1.2458x; 1.2458x over previous
#include <cuda_runtime.h>

// DiffJPEG forward: out = jpeg_compress(clip(x,0,1), quality=75)
// x, out: (16, 3, 512, 512) float32
//
// One CTA per 32x16 pixel region: 8 Y blocks + 2 Cb + 2 Cr (12 blocks of 8x8).
// 96 threads, one thread per block-row. Coalesced staged input AND output;
// dot-product DCT/IDCT with immediate coefficients; scalar SMEM transposes.

#define IMG_H 512
#define IMG_W 512
#define BATCH 16

#define A1 0.4903926402016152f
#define A2 0.4619397662556434f
#define A3 0.4157348061512726f
#define A4 0.3535533905932738f
#define A5 0.2777851165098011f
#define A6 0.1913417161825449f
#define A7 0.0975451610080642f

__device__ constexpr float Dm[8][8] = {
    { A4,  A4,  A4,  A4,  A4,  A4,  A4,  A4},
    { A1,  A3,  A5,  A7, -A7, -A5, -A3, -A1},
    { A2,  A6, -A6, -A2, -A2, -A6,  A6,  A2},
    { A3, -A7, -A1, -A5,  A5,  A1,  A7, -A3},
    { A4, -A4, -A4,  A4,  A4, -A4, -A4,  A4},
    { A5, -A1,  A7,  A3, -A3, -A7,  A1, -A5},
    { A6, -A2,  A2, -A6, -A6,  A2, -A2,  A6},
    { A7, -A5,  A3, -A1,  A1, -A3,  A5, -A7},
};

__constant__ float c_QY[8][8] = {
    {16, 11, 10, 16, 24, 40, 51, 61},
    {12, 12, 14, 19, 26, 58, 60, 55},
    {14, 13, 16, 24, 40, 57, 69, 56},
    {14, 17, 22, 29, 51, 87, 80, 62},
    {18, 22, 37, 56, 68, 109, 103, 77},
    {24, 35, 55, 64, 81, 104, 113, 92},
    {49, 64, 78, 87, 103, 121, 120, 101},
    {72, 92, 95, 98, 112, 100, 103, 99},
};
__constant__ float c_QC[8][8] = {
    {17, 18, 24, 47, 99, 99, 99, 99},
    {18, 21, 26, 66, 99, 99, 99, 99},
    {24, 26, 56, 99, 99, 99, 99, 99},
    {47, 66, 99, 99, 99, 99, 99, 99},
    {99, 99, 99, 99, 99, 99, 99, 99},
    {99, 99, 99, 99, 99, 99, 99, 99},
    {99, 99, 99, 99, 99, 99, 99, 99},
    {99, 99, 99, 99, 99, 99, 99, 99},
};

// Full fwd-DCT -> quantize -> inv-DCT; thread holds row r of the block.
// S: per-block 8x9 transpose scratch; Q/Qi: quant table and reciprocal.
__device__ __forceinline__ void transform8(float v[8], float (*S)[9],
                                           const float (*Q)[9],
                                           const float (*Qi)[9], int r)
{
    float t[8], m[8];
    // row DCT: t[j] = sum_k v[k] * D[j][k]
#pragma unroll
    for (int j = 0; j < 8; j++) {
        float s = 0.f;
#pragma unroll
        for (int k = 0; k < 8; k++) s += v[k] * Dm[j][k];
        t[j] = s;
    }
#pragma unroll
    for (int j = 0; j < 8; j++) S[j][r] = t[j];
    __syncwarp();
#pragma unroll
    for (int j = 0; j < 8; j++) t[j] = S[r][j];
    __syncwarp();
    // column DCT -> coef[j][r]
#pragma unroll
    for (int j = 0; j < 8; j++) {
        float s = 0.f;
#pragma unroll
        for (int k = 0; k < 8; k++) s += t[k] * Dm[j][k];
        m[j] = s;
    }
    // quantize coef[j][r]
#pragma unroll
    for (int j = 0; j < 8; j++)
        m[j] = rintf(m[j] * Qi[j][r]) * Q[j][r];
    // column IDCT
#pragma unroll
    for (int j = 0; j < 8; j++) {
        float s = 0.f;
#pragma unroll
        for (int k = 0; k < 8; k++) s += m[k] * Dm[k][j];
        t[j] = s;
    }
#pragma unroll
    for (int j = 0; j < 8; j++) S[j][r] = t[j];
    __syncwarp();
#pragma unroll
    for (int j = 0; j < 8; j++) t[j] = S[r][j];
    __syncwarp();
    // row IDCT -> rec row r
#pragma unroll
    for (int j = 0; j < 8; j++) {
        float s = 0.f;
#pragma unroll
        for (int k = 0; k < 8; k++) s += t[k] * Dm[k][j];
        v[j] = s;
    }
}

__global__ __launch_bounds__(96, 12)
void diffjpeg_kernel(const float* __restrict__ x, float* __restrict__ out)
{
    __shared__ __align__(16) float sIn[3][16][36];  // staged RGB tile (16B-aligned rows)
    __shared__ float sP[2][16][20];     // horizontally-averaged chroma partials
    __shared__ float sS[12][8][9];      // per-block transpose scratch
    __shared__ float sQ[2][8][9];       // quant tables * factor
    __shared__ float sQi[2][8][9];      // reciprocals
    __shared__ __align__(16) float sYrec[16][36];     // reconstructed luma (+128)
    __shared__ __align__(16) float sCrec[2][8][20];   // reconstructed chroma

    const int tid = threadIdx.x;
    const int bx0 = blockIdx.x * 32;
    const int by0 = blockIdx.y * 16;
    const size_t plane  = (size_t)IMG_H * IMG_W;
    const size_t ibase  = (size_t)blockIdx.z * 3 * plane;

    if (tid < 64) {
        int u = tid >> 3, vv = tid & 7;
        float qy = c_QY[u][vv] * 0.5f;   // quality 75 -> factor 0.5
        float qc = c_QC[u][vv] * 0.5f;
        sQ[0][u][vv]  = qy;
        sQ[1][u][vv]  = qc;
        sQi[0][u][vv] = 1.0f / qy;
        sQi[1][u][vv] = 1.0f / qc;
    }

    // ---- coalesced input staging: 384 float4s over 96 threads (4 each) ----
    {
        const float* src = x + ibase + (size_t)by0 * IMG_W + bx0;
#pragma unroll
        for (int it = 0; it < 4; it++) {
            int f   = tid + it * 96;          // 0..383
            int ch  = f >> 7;                 // 0..2
            int rem = f & 127;
            int row = rem >> 3, c4 = rem & 7;
            float4 val = *(const float4*)(src + (size_t)ch * plane +
                                          (size_t)row * IMG_W + c4 * 4);
            *(float4*)&sIn[ch][row][c4 * 4] = val;
        }
    }
    __syncthreads();

    // luma geometry
    const int blk  = tid >> 3, r = tid & 7;
    const int bcol = blk & 3,  brow = blk >> 2;
    const int lrow = brow * 8 + r;

    float v[8];

    if (tid < 64) {
        // ---- luma: read row from staged tile, color convert ----
        float cbh[4], crh[4];
#pragma unroll
        for (int h = 0; h < 2; h++) {
            float4 R4 = *(const float4*)&sIn[0][lrow][bcol * 8 + 4 * h];
            float4 G4 = *(const float4*)&sIn[1][lrow][bcol * 8 + 4 * h];
            float4 B4 = *(const float4*)&sIn[2][lrow][bcol * 8 + 4 * h];
            float R[4] = {R4.x, R4.y, R4.z, R4.w};
            float G[4] = {G4.x, G4.y, G4.z, G4.w};
            float B[4] = {B4.x, B4.y, B4.z, B4.w};
            float cb[4], cr[4];
#pragma unroll
            for (int k = 0; k < 4; k++) {
                float rr = fminf(fmaxf(R[k], 0.f), 1.f) * 255.f;
                float gg = fminf(fmaxf(G[k], 0.f), 1.f) * 255.f;
                float bb = fminf(fmaxf(B[k], 0.f), 1.f) * 255.f;
                v[4 * h + k] =  0.299f    * rr + 0.587f    * gg + 0.114f    * bb - 128.f;
                cb[k]        = -0.168736f * rr - 0.331264f * gg + 0.5f      * bb + 128.f;
                cr[k]        =  0.5f      * rr - 0.418688f * gg - 0.081312f * bb + 128.f;
            }
            cbh[2 * h]     = 0.5f * (cb[0] + cb[1]);
            cbh[2 * h + 1] = 0.5f * (cb[2] + cb[3]);
            crh[2 * h]     = 0.5f * (cr[0] + cr[1]);
            crh[2 * h + 1] = 0.5f * (cr[2] + cr[3]);
        }
        *(float4*)&sP[0][lrow][bcol * 4] = make_float4(cbh[0], cbh[1], cbh[2], cbh[3]);
        *(float4*)&sP[1][lrow][bcol * 4] = make_float4(crh[0], crh[1], crh[2], crh[3]);
    }
    __syncthreads();

    if (tid < 64) {
        transform8(v, sS[blk], sQ[0], sQi[0], r);

        *(float4*)&sYrec[lrow][bcol * 8] =
            make_float4(v[0] + 128.f, v[1] + 128.f, v[2] + 128.f, v[3] + 128.f);
        *(float4*)&sYrec[lrow][bcol * 8 + 4] =
            make_float4(v[4] + 128.f, v[5] + 128.f, v[6] + 128.f, v[7] + 128.f);
    } else {
        // ---- chroma: finish 2x2 downsample, transform, publish ----
        const int t  = tid - 64;
        const int ch = t >> 4;
        const int s2 = t & 15;
        const int bc = s2 >> 3, cr_ = s2 & 7;

        float4 a0 = *(const float4*)&sP[ch][2 * cr_][bc * 8];
        float4 a1 = *(const float4*)&sP[ch][2 * cr_][bc * 8 + 4];
        float4 b0 = *(const float4*)&sP[ch][2 * cr_ + 1][bc * 8];
        float4 b1 = *(const float4*)&sP[ch][2 * cr_ + 1][bc * 8 + 4];

        v[0] = 0.5f * (a0.x + b0.x) - 128.f;
        v[1] = 0.5f * (a0.y + b0.y) - 128.f;
        v[2] = 0.5f * (a0.z + b0.z) - 128.f;
        v[3] = 0.5f * (a0.w + b0.w) - 128.f;
        v[4] = 0.5f * (a1.x + b1.x) - 128.f;
        v[5] = 0.5f * (a1.y + b1.y) - 128.f;
        v[6] = 0.5f * (a1.z + b1.z) - 128.f;
        v[7] = 0.5f * (a1.w + b1.w) - 128.f;

        transform8(v, sS[8 + ch * 2 + bc], sQ[1], sQi[1], cr_);

        *(float4*)&sCrec[ch][cr_][bc * 8]     = make_float4(v[0], v[1], v[2], v[3]);
        *(float4*)&sCrec[ch][cr_][bc * 8 + 4] = make_float4(v[4], v[5], v[6], v[7]);
    }
    __syncthreads();

    // ---- coalesced output: upsample chroma, YCbCr -> RGB, clip, store ----
    const size_t obase = ibase + (size_t)by0 * IMG_W + bx0;
#pragma unroll
    for (int f = tid; f < 128; f += 96) {
        int row = f >> 3, c4 = f & 7;
        float4 yv = *(const float4*)&sYrec[row][c4 * 4];
        int crow = row >> 1, cc = c4 * 2;
        float cb0 = sCrec[0][crow][cc], cb1 = sCrec[0][crow][cc + 1];
        float cr0 = sCrec[1][crow][cc], cr1 = sCrec[1][crow][cc + 1];

        float yy[4]  = {yv.x, yv.y, yv.z, yv.w};
        float cbm[4] = {cb0, cb0, cb1, cb1};
        float crm[4] = {cr0, cr0, cr1, cr1};

        float4 Ro, Go, Bo;
        float* Rp = &Ro.x; float* Gp = &Go.x; float* Bp = &Bo.x;
#pragma unroll
        for (int i = 0; i < 4; i++) {
            float r2 = yy[i] + 1.402f * crm[i];
            float g2 = yy[i] - 0.344136f * cbm[i] - 0.714136f * crm[i];
            float b2 = yy[i] + 1.772f * cbm[i];
            Rp[i] = fminf(fmaxf(r2, 0.f), 255.f) * (1.f / 255.f);
            Gp[i] = fminf(fmaxf(g2, 0.f), 255.f) * (1.f / 255.f);
            Bp[i] = fminf(fmaxf(b2, 0.f), 255.f) * (1.f / 255.f);
        }
        size_t o = obase + (size_t)row * IMG_W + c4 * 4;
        *(float4*)(out + o)             = Ro;
        *(float4*)(out + o + plane)     = Go;
        *(float4*)(out + o + 2 * plane) = Bo;
    }
}

extern "C" void kernel_launch(void* const* d_in, const int* in_sizes, int n_in,
                              void* d_out, int out_size)
{
    const float* x = (const float*)d_in[0];
    float* out = (float*)d_out;
    dim3 grid(IMG_W / 32, IMG_H / 16, BATCH);
    diffjpeg_kernel<<<grid, 96>>>(x, out);
}

// round 11
// speedup vs baseline: 1.3706x; 1.1002x over previous
#include <cuda_runtime.h>

// DiffJPEG forward: out = jpeg_compress(clip(x,0,1), quality=75)
// x, out: (16, 3, 512, 512) float32
//
// One CTA per 32x16 pixel region: 8 Y blocks + 2 Cb + 2 Cr (12 blocks of 8x8).
// 96 threads, one thread per block-row. Coalesced staged input AND output;
// butterfly DCT/IDCT (40 ops/line); saturate-modifier clamps; scalar SMEM
// transposes.

#define IMG_H 512
#define IMG_W 512
#define BATCH 16

#define A1 0.4903926402016152f
#define A2 0.4619397662556434f
#define A3 0.4157348061512726f
#define A4 0.3535533905932738f
#define A5 0.2777851165098011f
#define A6 0.1913417161825449f
#define A7 0.0975451610080642f

__constant__ float c_QY[8][8] = {
    {16, 11, 10, 16, 24, 40, 51, 61},
    {12, 12, 14, 19, 26, 58, 60, 55},
    {14, 13, 16, 24, 40, 57, 69, 56},
    {14, 17, 22, 29, 51, 87, 80, 62},
    {18, 22, 37, 56, 68, 109, 103, 77},
    {24, 35, 55, 64, 81, 104, 113, 92},
    {49, 64, 78, 87, 103, 121, 120, 101},
    {72, 92, 95, 98, 112, 100, 103, 99},
};
__constant__ float c_QC[8][8] = {
    {17, 18, 24, 47, 99, 99, 99, 99},
    {18, 21, 26, 66, 99, 99, 99, 99},
    {24, 26, 56, 99, 99, 99, 99, 99},
    {47, 66, 99, 99, 99, 99, 99, 99},
    {99, 99, 99, 99, 99, 99, 99, 99},
    {99, 99, 99, 99, 99, 99, 99, 99},
    {99, 99, 99, 99, 99, 99, 99, 99},
    {99, 99, 99, 99, 99, 99, 99, 99},
};

// forward 8-point DCT-II: out[u] = sum_x D[u][x] in[x], in place
__device__ __forceinline__ void fwd1d(float d[8])
{
    float s0 = d[0] + d[7], s1 = d[1] + d[6], s2 = d[2] + d[5], s3 = d[3] + d[4];
    float t0 = d[0] - d[7], t1 = d[1] - d[6], t2 = d[2] - d[5], t3 = d[3] - d[4];
    d[0] = A4 * (s0 + s1 + s2 + s3);
    d[2] = A2 * s0 + A6 * s1 - A6 * s2 - A2 * s3;
    d[4] = A4 * (s0 - s1 - s2 + s3);
    d[6] = A6 * s0 - A2 * s1 + A2 * s2 - A6 * s3;
    d[1] = A1 * t0 + A3 * t1 + A5 * t2 + A7 * t3;
    d[3] = A3 * t0 - A7 * t1 - A1 * t2 - A5 * t3;
    d[5] = A5 * t0 - A1 * t1 + A7 * t2 + A3 * t3;
    d[7] = A7 * t0 - A5 * t1 + A3 * t2 - A1 * t3;
}

// inverse: out[x] = sum_u D[u][x] in[u], in place
__device__ __forceinline__ void inv1d(float d[8])
{
    float e0 = A4 * d[0] + A2 * d[2] + A4 * d[4] + A6 * d[6];
    float e1 = A4 * d[0] + A6 * d[2] - A4 * d[4] - A2 * d[6];
    float e2 = A4 * d[0] - A6 * d[2] - A4 * d[4] + A2 * d[6];
    float e3 = A4 * d[0] - A2 * d[2] + A4 * d[4] - A6 * d[6];
    float o0 = A1 * d[1] + A3 * d[3] + A5 * d[5] + A7 * d[7];
    float o1 = A3 * d[1] - A7 * d[3] - A1 * d[5] - A5 * d[7];
    float o2 = A5 * d[1] - A1 * d[3] + A7 * d[5] + A3 * d[7];
    float o3 = A7 * d[1] - A5 * d[3] + A3 * d[5] - A1 * d[7];
    d[0] = e0 + o0; d[7] = e0 - o0;
    d[1] = e1 + o1; d[6] = e1 - o1;
    d[2] = e2 + o2; d[5] = e2 - o2;
    d[3] = e3 + o3; d[4] = e3 - o3;
}

// Full fwd-DCT -> quantize -> inv-DCT; thread holds row r of the block.
__device__ __forceinline__ void transform8(float v[8], float (*S)[9],
                                           const float (*Q)[9],
                                           const float (*Qi)[9], int r)
{
    fwd1d(v);                                   // row DCT
#pragma unroll
    for (int j = 0; j < 8; j++) S[j][r] = v[j]; // transpose 1
    __syncwarp();
#pragma unroll
    for (int j = 0; j < 8; j++) v[j] = S[r][j];
    __syncwarp();
    fwd1d(v);                                   // column DCT -> coef[j][r]
#pragma unroll
    for (int j = 0; j < 8; j++)
        v[j] = rintf(v[j] * Qi[j][r]) * Q[j][r];
    inv1d(v);                                   // column IDCT
#pragma unroll
    for (int j = 0; j < 8; j++) S[j][r] = v[j]; // transpose 2
    __syncwarp();
#pragma unroll
    for (int j = 0; j < 8; j++) v[j] = S[r][j];
    __syncwarp();
    inv1d(v);                                   // row IDCT -> rec row r
}

__global__ __launch_bounds__(96, 14)
void diffjpeg_kernel(const float* __restrict__ x, float* __restrict__ out)
{
    __shared__ __align__(16) float sIn[3][16][36];  // staged RGB tile
    __shared__ float sP[2][16][20];     // horizontally-averaged chroma partials
    __shared__ float sS[12][8][9];      // per-block transpose scratch
    __shared__ float sQ[2][8][9];       // quant tables * factor
    __shared__ float sQi[2][8][9];      // reciprocals
    __shared__ __align__(16) float sYrec[16][36];     // reconstructed luma (+128)
    __shared__ __align__(16) float sCrec[2][8][20];   // reconstructed chroma

    const int tid = threadIdx.x;
    const int bx0 = blockIdx.x * 32;
    const int by0 = blockIdx.y * 16;
    const size_t plane  = (size_t)IMG_H * IMG_W;
    const size_t ibase  = (size_t)blockIdx.z * 3 * plane;

    if (tid < 64) {
        int u = tid >> 3, vv = tid & 7;
        float qy = c_QY[u][vv] * 0.5f;   // quality 75 -> factor 0.5
        float qc = c_QC[u][vv] * 0.5f;
        sQ[0][u][vv]  = qy;
        sQ[1][u][vv]  = qc;
        sQi[0][u][vv] = 1.0f / qy;
        sQi[1][u][vv] = 1.0f / qc;
    }

    // ---- coalesced input staging: 384 float4s over 96 threads (4 each) ----
    {
        const float* src = x + ibase + (size_t)by0 * IMG_W + bx0;
#pragma unroll
        for (int it = 0; it < 4; it++) {
            int f   = tid + it * 96;          // 0..383
            int ch  = f >> 7;                 // 0..2
            int rem = f & 127;
            int row = rem >> 3, c4 = rem & 7;
            float4 val = *(const float4*)(src + (size_t)ch * plane +
                                          (size_t)row * IMG_W + c4 * 4);
            *(float4*)&sIn[ch][row][c4 * 4] = val;
        }
    }
    __syncthreads();

    // luma geometry
    const int blk  = tid >> 3, r = tid & 7;
    const int bcol = blk & 3,  brow = blk >> 2;
    const int lrow = brow * 8 + r;

    float v[8];

    if (tid < 64) {
        // ---- luma: read row from staged tile, color convert ----
        float cbh[4], crh[4];
#pragma unroll
        for (int h = 0; h < 2; h++) {
            float4 R4 = *(const float4*)&sIn[0][lrow][bcol * 8 + 4 * h];
            float4 G4 = *(const float4*)&sIn[1][lrow][bcol * 8 + 4 * h];
            float4 B4 = *(const float4*)&sIn[2][lrow][bcol * 8 + 4 * h];
            float R[4] = {R4.x, R4.y, R4.z, R4.w};
            float G[4] = {G4.x, G4.y, G4.z, G4.w};
            float B[4] = {B4.x, B4.y, B4.z, B4.w};
            float cb[4], cr[4];
#pragma unroll
            for (int k = 0; k < 4; k++) {
                float rr = __saturatef(R[k]) * 255.f;   // clip folded into FMUL.SAT
                float gg = __saturatef(G[k]) * 255.f;
                float bb = __saturatef(B[k]) * 255.f;
                v[4 * h + k] =  0.299f    * rr + 0.587f    * gg + 0.114f    * bb - 128.f;
                cb[k]        = -0.168736f * rr - 0.331264f * gg + 0.5f      * bb + 128.f;
                cr[k]        =  0.5f      * rr - 0.418688f * gg - 0.081312f * bb + 128.f;
            }
            cbh[2 * h]     = 0.5f * (cb[0] + cb[1]);
            cbh[2 * h + 1] = 0.5f * (cb[2] + cb[3]);
            crh[2 * h]     = 0.5f * (cr[0] + cr[1]);
            crh[2 * h + 1] = 0.5f * (cr[2] + cr[3]);
        }
        *(float4*)&sP[0][lrow][bcol * 4] = make_float4(cbh[0], cbh[1], cbh[2], cbh[3]);
        *(float4*)&sP[1][lrow][bcol * 4] = make_float4(crh[0], crh[1], crh[2], crh[3]);
    }
    __syncthreads();

    if (tid < 64) {
        transform8(v, sS[blk], sQ[0], sQi[0], r);

        *(float4*)&sYrec[lrow][bcol * 8] =
            make_float4(v[0] + 128.f, v[1] + 128.f, v[2] + 128.f, v[3] + 128.f);
        *(float4*)&sYrec[lrow][bcol * 8 + 4] =
            make_float4(v[4] + 128.f, v[5] + 128.f, v[6] + 128.f, v[7] + 128.f);
    } else {
        // ---- chroma: finish 2x2 downsample, transform, publish ----
        const int t  = tid - 64;
        const int ch = t >> 4;
        const int s2 = t & 15;
        const int bc = s2 >> 3, cr_ = s2 & 7;

        float4 a0 = *(const float4*)&sP[ch][2 * cr_][bc * 8];
        float4 a1 = *(const float4*)&sP[ch][2 * cr_][bc * 8 + 4];
        float4 b0 = *(const float4*)&sP[ch][2 * cr_ + 1][bc * 8];
        float4 b1 = *(const float4*)&sP[ch][2 * cr_ + 1][bc * 8 + 4];

        v[0] = 0.5f * (a0.x + b0.x) - 128.f;
        v[1] = 0.5f * (a0.y + b0.y) - 128.f;
        v[2] = 0.5f * (a0.z + b0.z) - 128.f;
        v[3] = 0.5f * (a0.w + b0.w) - 128.f;
        v[4] = 0.5f * (a1.x + b1.x) - 128.f;
        v[5] = 0.5f * (a1.y + b1.y) - 128.f;
        v[6] = 0.5f * (a1.z + b1.z) - 128.f;
        v[7] = 0.5f * (a1.w + b1.w) - 128.f;

        transform8(v, sS[8 + ch * 2 + bc], sQ[1], sQi[1], cr_);

        *(float4*)&sCrec[ch][cr_][bc * 8]     = make_float4(v[0], v[1], v[2], v[3]);
        *(float4*)&sCrec[ch][cr_][bc * 8 + 4] = make_float4(v[4], v[5], v[6], v[7]);
    }
    __syncthreads();

    // ---- coalesced output: upsample chroma, YCbCr -> RGB, clip, store ----
    const size_t obase = ibase + (size_t)by0 * IMG_W + bx0;
#pragma unroll
    for (int f = tid; f < 128; f += 96) {
        int row = f >> 3, c4 = f & 7;
        float4 yv = *(const float4*)&sYrec[row][c4 * 4];
        int crow = row >> 1, cc = c4 * 2;
        float cb0 = sCrec[0][crow][cc], cb1 = sCrec[0][crow][cc + 1];
        float cr0 = sCrec[1][crow][cc], cr1 = sCrec[1][crow][cc + 1];

        float yy[4]  = {yv.x, yv.y, yv.z, yv.w};
        float cbm[4] = {cb0, cb0, cb1, cb1};
        float crm[4] = {cr0, cr0, cr1, cr1};

        float4 Ro, Go, Bo;
        float* Rp = &Ro.x; float* Gp = &Go.x; float* Bp = &Bo.x;
#pragma unroll
        for (int i = 0; i < 4; i++) {
            float r2 = yy[i] + 1.402f * crm[i];
            float g2 = yy[i] - 0.344136f * cbm[i] - 0.714136f * crm[i];
            float b2 = yy[i] + 1.772f * cbm[i];
            Rp[i] = __saturatef(r2 * (1.f / 255.f));   // clip folded into FMUL.SAT
            Gp[i] = __saturatef(g2 * (1.f / 255.f));
            Bp[i] = __saturatef(b2 * (1.f / 255.f));
        }
        size_t o = obase + (size_t)row * IMG_W + c4 * 4;
        *(float4*)(out + o)             = Ro;
        *(float4*)(out + o + plane)     = Go;
        *(float4*)(out + o + 2 * plane) = Bo;
    }
}

extern "C" void kernel_launch(void* const* d_in, const int* in_sizes, int n_in,
                              void* d_out, int out_size)
{
    const float* x = (const float*)d_in[0];
    float* out = (float*)d_out;
    dim3 grid(IMG_W / 32, IMG_H / 16, BATCH);
    diffjpeg_kernel<<<grid, 96>>>(x, out);
}